// round 17
// baseline (speedup 1.0000x reference)
#include <cuda_runtime.h>

#define H      128
#define W      128
#define NLAM   128
#define BATCH  16
#define NK     4
#define HP     192
#define WP     192

// padded staging buffer: per (b,l) slice is HPAD x WPAD with the 128x128 data
// at (YOFF, XOFF); borders are zero (static init, never written).
#define WPAD   256
#define HPAD   240
#define XOFF   80
#define YOFF   80
#define SLICE  (HPAD * WPAD)

__device__ float g_pad[(size_t)BATCH * NLAM * SLICE];   // ~503 MB, zero-initialized

#define QTRSZ (BATCH * NK * HP * WP)
__device__ float g_acc[4 * QTRSZ];

// ---------------------------------------------------------------------------
// Kernel 0: stage cube into padded buffer (borders stay zero forever).
// Grid: B*NLAM blocks, 256 threads; each block copies one 128x128 slice.
// ---------------------------------------------------------------------------
__global__ __launch_bounds__(256) void pad_kernel(const float* __restrict__ cube)
{
    const int s = blockIdx.x;                    // b*NLAM + l
    const float* src = cube + (size_t)s * (H * W);
    float* dst = g_pad + (size_t)s * SLICE + YOFF * WPAD + XOFF;
    for (int i = threadIdx.x; i < H * (W / 4); i += 256) {
        int r = i >> 5;            // W/4 = 32 float4 per row
        int c = (i & 31) << 2;
        *(float4*)(dst + r * WPAD + c) = *(const float4*)(src + r * W + c);
    }
}

// ---------------------------------------------------------------------------
// Kernel 1: accumulate shifted slices over one quarter (32) of the wavelengths.
// Block: 192 threads = 6 warps (3x in x, 2x in y); warp = 64 cols x 4 rows,
// lane owns 2 consecutive cols. Grid (1, 24, 256). 6144 blocks.
// All loads hit the padded buffer -> no bounds checks, no edge paths.
// Per-lambda address = warp_base + s_off[l] (one LDS + one IADD).
// ---------------------------------------------------------------------------
__global__ __launch_bounds__(192) void accum_kernel(
    const float* __restrict__ dx,     // (NK, NLAM)
    const float* __restrict__ dy)     // (NK, NLAM)
{
    __shared__ int    s_nx[32], s_ny[32], s_off[32];
    __shared__ float4 s_w[32];        // (fx, gx, fy, gy) / k=1: (fy*wdom, gy*wdom, -, -)

    const int bz = blockIdx.z;
    const int lq = bz & 3;            // lambda quarter
    const int bk = bz >> 2;           // b*4 + k
    const int b  = bk >> 2;
    const int k  = bk & 3;
    const int l0 = lq * 32;

    const int tid = threadIdx.y * 32 + threadIdx.x;
    if (tid < 32) {
        float dxv = dx[k * NLAM + l0 + tid];
        float dyv = dy[k * NLAM + l0 + tid];
        float nxf = floorf(dxv), nyf = floorf(dyv);
        int nx = (int)nxf, ny = (int)nyf;
        float fx = dxv - nxf, fy = dyv - nyf;
        float gx = 1.0f - fx, gy = 1.0f - fy;
        s_nx[tid] = nx;
        s_ny[tid] = ny;
        if (k == 1) {
            // dominant x-tap only (minor tap weight <= 1.8e-6)
            int   cadj; float wdom;
            if (fx >= 0.5f) { cadj = -nx;     wdom = fx; }
            else            { cadj = 1 - nx;  wdom = gx; }
            s_off[tid] = tid * SLICE - ny * WPAD + cadj;
            s_w[tid] = make_float4(fy * wdom, gy * wdom, 0.0f, 0.0f);
        } else {
            s_off[tid] = tid * SLICE - ny * WPAD - nx;
            s_w[tid] = make_float4(fx, gx, fy, gy);
        }
    }
    __syncthreads();

    const int wid  = tid >> 5;        // 0..5
    const int lane = tid & 31;
    const int wx   = wid % 3;
    const int wy   = wid / 3;
    const int x0w  = wx * 64;                    // warp col base
    const int y0   = blockIdx.y * 8 + wy * 4;    // warp row base (4 rows)

    float a0[4], a1[4];
    #pragma unroll
    for (int i = 0; i < 4; ++i) { a0[i] = 0.0f; a1[i] = 0.0f; }

    const float* pb = g_pad + ((size_t)b * NLAM + l0) * SLICE;
    // warp base index into padded slice (includes lane)
    const int wb = (YOFF + y0 - 33) * WPAD + (XOFF - 33 + x0w) + 2 * lane;

    if (k == 0) {
        // pure horizontal (ny == 0): rows y0-32 .. y0-29 (j = 1..4), fy = 0
        const int ry0 = y0 - 33;
        if (!(ry0 + 1 > H - 1 || ry0 + 4 < 0)) {
            unsigned mask;
            {
                int t = x0w - 33 - s_nx[lane];
                mask = __ballot_sync(0xffffffffu, !(t > W - 1 || t + 64 < 0));
            }
            const int lmin = __ffs(mask) - 1;
            const int cnt  = __popc(mask);

            #pragma unroll 2
            for (int i = 0; i < cnt; ++i) {
                const int l = lmin + i;
                const float4 wv = s_w[l];
                const float fx = wv.x, gx = wv.y;
                const int idx = wb + s_off[l];
                const int o   = idx & 1;                  // warp-uniform
                const float* p = pb + (idx - o);
                if (o == 0) {
                    #pragma unroll
                    for (int j = 1; j <= 4; ++j) {
                        const float* rj = p + j * WPAD;
                        float2 A = __ldg((const float2*)rj);
                        float  c = __ldg(rj + 2);
                        a0[j - 1] += fx * A.x + gx * A.y;
                        a1[j - 1] += fx * A.y + gx * c;
                    }
                } else {
                    #pragma unroll
                    for (int j = 1; j <= 4; ++j) {
                        const float* rj = p + j * WPAD;
                        float2 A = __ldg((const float2*)rj);
                        float2 B = __ldg((const float2*)(rj + 2));
                        a0[j - 1] += fx * A.y + gx * B.x;
                        a1[j - 1] += fx * B.x + gx * B.y;
                    }
                }
            }
        }
    } else if (k == 1) {
        // pure vertical: single dominant column tap, rows j = 0..4 chained
        unsigned mask;
        {
            int ry = y0 - 33 - s_ny[lane];
            mask = __ballot_sync(0xffffffffu, !(ry > H - 1 || ry + 4 < 0));
        }
        const int lmin = __ffs(mask) - 1;
        const int cnt  = __popc(mask);

        #pragma unroll 2
        for (int i = 0; i < cnt; ++i) {
            const int l = lmin + i;
            const float4 wv = s_w[l];
            const float fyd = wv.x, gyd = wv.y;
            const int idx = wb + s_off[l];
            const int o   = idx & 1;
            const float* p = pb + (idx - o);
            if (o == 0) {
                float2 vp = __ldg((const float2*)p);
                #pragma unroll
                for (int j = 1; j <= 4; ++j) {
                    float2 vc = __ldg((const float2*)(p + j * WPAD));
                    a0[j - 1] += fyd * vp.x + gyd * vc.x;
                    a1[j - 1] += fyd * vp.y + gyd * vc.y;
                    vp = vc;
                }
            } else {
                float2 A = __ldg((const float2*)p);
                float2 B = __ldg((const float2*)(p + 2));
                float p0 = A.y, p1 = B.x;
                #pragma unroll
                for (int j = 1; j <= 4; ++j) {
                    float2 A2 = __ldg((const float2*)(p + j * WPAD));
                    float2 B2 = __ldg((const float2*)(p + j * WPAD + 2));
                    float c0 = A2.y, c1 = B2.x;
                    a0[j - 1] += fyd * p0 + gyd * c0;
                    a1[j - 1] += fyd * p1 + gyd * c1;
                    p0 = c0; p1 = c1;
                }
            }
        }
    } else {
        // full bilinear 4-tap (k = 2, 3), rows j = 0..4 with h-chaining
        unsigned mask;
        {
            int t  = x0w - 33 - s_nx[lane];
            int ry = y0  - 33 - s_ny[lane];
            mask = __ballot_sync(0xffffffffu,
                                 !(t > W - 1 || t + 64 < 0 || ry > H - 1 || ry + 4 < 0));
        }
        const int lmin = __ffs(mask) - 1;
        const int cnt  = __popc(mask);

        #pragma unroll 2
        for (int i = 0; i < cnt; ++i) {
            const int l = lmin + i;
            const float4 wv = s_w[l];
            const float fx = wv.x, gx = wv.y, fy = wv.z, gy = wv.w;
            const int idx = wb + s_off[l];
            const int o   = idx & 1;
            const float* p = pb + (idx - o);
            float hp0, hp1;
            if (o == 0) {
                {
                    float2 A = __ldg((const float2*)p);
                    float  c = __ldg(p + 2);
                    hp0 = fx * A.x + gx * A.y;
                    hp1 = fx * A.y + gx * c;
                }
                #pragma unroll
                for (int j = 1; j <= 4; ++j) {
                    const float* rj = p + j * WPAD;
                    float2 A = __ldg((const float2*)rj);
                    float  c = __ldg(rj + 2);
                    float hc0 = fx * A.x + gx * A.y;
                    float hc1 = fx * A.y + gx * c;
                    a0[j - 1] += fy * hp0 + gy * hc0;
                    a1[j - 1] += fy * hp1 + gy * hc1;
                    hp0 = hc0; hp1 = hc1;
                }
            } else {
                {
                    float2 A = __ldg((const float2*)p);
                    float2 B = __ldg((const float2*)(p + 2));
                    hp0 = fx * A.y + gx * B.x;
                    hp1 = fx * B.x + gx * B.y;
                }
                #pragma unroll
                for (int j = 1; j <= 4; ++j) {
                    const float* rj = p + j * WPAD;
                    float2 A = __ldg((const float2*)rj);
                    float2 B = __ldg((const float2*)(rj + 2));
                    float hc0 = fx * A.y + gx * B.x;
                    float hc1 = fx * B.x + gx * B.y;
                    a0[j - 1] += fy * hp0 + gy * hc0;
                    a1[j - 1] += fy * hp1 + gy * hc1;
                    hp0 = hc0; hp1 = hc1;
                }
            }
        }
    }

    float* ap = g_acc + (size_t)lq * QTRSZ + ((size_t)bk * HP + y0) * WP + x0w + 2 * lane;
    #pragma unroll
    for (int i = 0; i < 4; ++i)
        *(float2*)(ap + i * WP) = make_float2(a0[i], a1[i]);
}

// ---------------------------------------------------------------------------
// Kernel 2: 7x7 PSF convolution (same padding, zeros), sum of 4 acc -> out.
// Block: (32, 8), output tile 32x32. Grid: (6, 6, B*NK).
// ---------------------------------------------------------------------------
__global__ __launch_bounds__(256) void conv_kernel(
    const float* __restrict__ psf,
    float* __restrict__ out)
{
    __shared__ float s[38 * 40];
    __shared__ float sp[49];

    const int bz = blockIdx.z;
    const float* ap0 = g_acc + (size_t)bz * HP * WP;

    const int tid = threadIdx.y * 32 + threadIdx.x;
    if (tid < 49) sp[tid] = psf[tid];

    const int x0 = blockIdx.x * 32;
    const int y0 = blockIdx.y * 32;

    for (int i = tid; i < 38 * 38; i += 256) {
        int r = i / 38, c = i % 38;
        int gy = y0 + r - 3;
        int gx = x0 + c - 3;
        bool ok = ((unsigned)gy < (unsigned)HP) && ((unsigned)gx < (unsigned)WP);
        int idx = gy * WP + gx;
        float v = 0.0f;
        if (ok) {
            v = ap0[idx] + ap0[idx + QTRSZ] + ap0[idx + 2 * QTRSZ] + ap0[idx + 3 * QTRSZ];
        }
        s[r * 40 + c] = v;
    }
    __syncthreads();

    float w[49];
    #pragma unroll
    for (int i = 0; i < 49; ++i) w[i] = sp[i];

    const int tx = threadIdx.x;
    const int rbase = threadIdx.y * 4;

    float a0 = 0.f, a1 = 0.f, a2 = 0.f, a3 = 0.f;
    #pragma unroll
    for (int rr = 0; rr < 10; ++rr) {
        #pragma unroll
        for (int v = 0; v < 7; ++v) {
            float xv = s[(rbase + rr) * 40 + tx + v];
            if (rr <= 6)            a0 += w[rr * 7 + v] * xv;
            if (rr >= 1 && rr <= 7) a1 += w[(rr - 1) * 7 + v] * xv;
            if (rr >= 2 && rr <= 8) a2 += w[(rr - 2) * 7 + v] * xv;
            if (rr >= 3)            a3 += w[(rr - 3) * 7 + v] * xv;
        }
    }

    float* op = out + ((size_t)bz * HP + y0 + rbase) * WP + x0 + tx;
    op[0 * WP] = a0;
    op[1 * WP] = a1;
    op[2 * WP] = a2;
    op[3 * WP] = a3;
}

extern "C" void kernel_launch(void* const* d_in, const int* in_sizes, int n_in,
                              void* d_out, int out_size)
{
    const float* cube = (const float*)d_in[0];
    const float* psf  = (const float*)d_in[1];
    const float* dx   = (const float*)d_in[2];
    const float* dy   = (const float*)d_in[3];
    float* out = (float*)d_out;

    pad_kernel<<<BATCH * NLAM, 256>>>(cube);

    dim3 ga(1, 24, BATCH * NK * 4), ta(32, 6);   // 6144 blocks, 192 thr
    accum_kernel<<<ga, ta>>>(dx, dy);

    dim3 gc(6, 6, BATCH * NK), tc(32, 8);
    conv_kernel<<<gc, tc>>>(psf, out);
}